// round 14
// baseline (speedup 1.0000x reference)
#include <cuda_runtime.h>
#include <cuda_bf16.h>
#include <math.h>
#include <stdint.h>

// Problem constants
#define B_SZ   128
#define T_ENC  64
#define D_IN   2048
#define T_DEC  32
#define D_W    300
#define D_WP   320
#define H_SZ   512
#define G4     2048
#define M_ENC  (T_ENC * B_SZ)   // 8192
#define M_DEC  (T_DEC * B_SZ)   // 4096

// ---------------- scratch (device globals; no allocation) ----------------
__device__ float g_Xg_enc[(size_t)M_ENC * G4];
__device__ float g_Xg_dec[(size_t)M_DEC * G4];
__device__ float g_P    [4 * B_SZ * G4];     // split-K partials, gate-interleaved cols (u*4+g)
__device__ float g_c    [B_SZ * H_SZ];
__device__ unsigned g_bar4[4 * 64];          // 4 split barrier counters, 256B apart

// bf16 limb arrays (16B aligned)
__device__ __align__(16) __nv_bfloat16 g_hl  [2][2][B_SZ * H_SZ];     // [parity][limb] recurrent h
__device__ __align__(16) __nv_bfloat16 g_WhT [2][2][(size_t)G4 * H_SZ]; // [enc/dec][limb] Wh^T rows u*4+g
__device__ __align__(16) __nv_bfloat16 g_Afr_h[(size_t)M_ENC * D_IN];
__device__ __align__(16) __nv_bfloat16 g_Afr_l[(size_t)M_ENC * D_IN];
__device__ __align__(16) __nv_bfloat16 g_Bte_h[(size_t)G4 * D_IN];
__device__ __align__(16) __nv_bfloat16 g_Bte_l[(size_t)G4 * D_IN];
__device__ __align__(16) __nv_bfloat16 g_Ad_h [(size_t)M_DEC * D_WP];
__device__ __align__(16) __nv_bfloat16 g_Ad_l [(size_t)M_DEC * D_WP];
__device__ __align__(16) __nv_bfloat16 g_Btd_h[(size_t)G4 * D_WP];
__device__ __align__(16) __nv_bfloat16 g_Btd_l[(size_t)G4 * D_WP];
__device__ __align__(16) __nv_bfloat16 g_Dh_h [(size_t)M_DEC * H_SZ];
__device__ __align__(16) __nv_bfloat16 g_Dh_l [(size_t)M_DEC * H_SZ];
__device__ __align__(16) __nv_bfloat16 g_Bto_h[(size_t)512 * H_SZ];
__device__ __align__(16) __nv_bfloat16 g_Bto_l[(size_t)512 * H_SZ];

// fast activations: __expf/__fdividef (rel err ~1e-7), saturate correctly at +-inf
__device__ __forceinline__ float fsig_(float x) {
    return __fdividef(1.0f, 1.0f + __expf(-x));
}
__device__ __forceinline__ float ftanh_(float x) {
    return 1.0f - __fdividef(2.0f, __expf(2.0f * x) + 1.0f);
}

// ============================ PTX helpers (baseline ISA) ============================
__device__ __forceinline__ uint32_t smem_u32_(const void* p) {
    uint32_t a;
    asm("{ .reg .u64 t; cvta.to.shared.u64 t, %1; cvt.u32.u64 %0, t; }" : "=r"(a) : "l"(p));
    return a;
}
__device__ __forceinline__ void cp16_(uint32_t dst, const void* src) {
    asm volatile("cp.async.cg.shared.global [%0], [%1], 16;" :: "r"(dst), "l"(src));
}
__device__ __forceinline__ void cp_commit_() { asm volatile("cp.async.commit_group;" ::: "memory"); }
__device__ __forceinline__ void cp_wait0_()  { asm volatile("cp.async.wait_group 0;" ::: "memory"); }
__device__ __forceinline__ void cp_wait1_()  { asm volatile("cp.async.wait_group 1;" ::: "memory"); }

__device__ __forceinline__ void ldm4_(uint32_t* r, uint32_t addr) {
    asm volatile("ldmatrix.sync.aligned.m8n8.x4.shared.b16 {%0,%1,%2,%3}, [%4];"
                 : "=r"(r[0]), "=r"(r[1]), "=r"(r[2]), "=r"(r[3]) : "r"(addr));
}
__device__ __forceinline__ void mma16816_(float* d, const uint32_t* a, uint32_t b0, uint32_t b1) {
    asm volatile("mma.sync.aligned.m16n8k16.row.col.f32.bf16.bf16.f32 "
                 "{%0,%1,%2,%3}, {%4,%5,%6,%7}, {%8,%9}, {%0,%1,%2,%3};"
                 : "+f"(d[0]), "+f"(d[1]), "+f"(d[2]), "+f"(d[3])
                 : "r"(a[0]), "r"(a[1]), "r"(a[2]), "r"(a[3]), "r"(b0), "r"(b1));
}

// grid barrier, 128 CTAs, 4 split counters (32 arrivals each) to cut atomic contention.
// Monotonic counters -> graph-replay safe.
__device__ __forceinline__ void grid_bar4_(int ks) {
    __threadfence();
    __syncthreads();
    if (threadIdx.x == 0) {
        unsigned old = atomicAdd(&g_bar4[ks * 64], 1u);
        unsigned target = ((old >> 5) + 1u) << 5;
#pragma unroll
        for (int k = 0; k < 4; k++) {
            while ((int)(target - *((volatile unsigned*)&g_bar4[k * 64])) > 0) {}
        }
    }
    __syncthreads();
}

// ============================ mma.sync bf16 2-limb GEMM (2-stage, occ 2) ============================
// C[M,N] = (Ah+Al)[M,Ka] @ (Bh+Bl)[N,Ka]^T + bias  (drop Al*Bl).
// BM=128, BN=128, BK=32. Stage: Ah@0 Al@10240 Bh@20480 Bl@30720 (row stride 80B).
#define GTS_SMEM (2 * 40960)

__device__ __forceinline__ void gts_pf_(uint32_t sb,
    const __nv_bfloat16* Ah, const __nv_bfloat16* Al,
    const __nv_bfloat16* Bh, const __nv_bfloat16* Bl,
    int m0, int n0, int k0, int Ka, int lrow0, int lg0, int lrow1, int lg1)
{
    uint32_t o0 = (uint32_t)(lrow0 * 80 + lg0 * 16);
    uint32_t o1 = (uint32_t)(lrow1 * 80 + lg1 * 16);
    cp16_(sb + o0,         Ah + (size_t)(m0 + lrow0) * Ka + k0 + lg0 * 8);
    cp16_(sb + o1,         Ah + (size_t)(m0 + lrow1) * Ka + k0 + lg1 * 8);
    cp16_(sb + 10240 + o0, Al + (size_t)(m0 + lrow0) * Ka + k0 + lg0 * 8);
    cp16_(sb + 10240 + o1, Al + (size_t)(m0 + lrow1) * Ka + k0 + lg1 * 8);
    cp16_(sb + 20480 + o0, Bh + (size_t)(n0 + lrow0) * Ka + k0 + lg0 * 8);
    cp16_(sb + 20480 + o1, Bh + (size_t)(n0 + lrow1) * Ka + k0 + lg1 * 8);
    cp16_(sb + 30720 + o0, Bl + (size_t)(n0 + lrow0) * Ka + k0 + lg0 * 8);
    cp16_(sb + 30720 + o1, Bl + (size_t)(n0 + lrow1) * Ka + k0 + lg1 * 8);
    cp_commit_();
}

template <int CMODE>
__global__ __launch_bounds__(256, 2)
void gemm_ts(const __nv_bfloat16* __restrict__ Ah, const __nv_bfloat16* __restrict__ Al,
             const __nv_bfloat16* __restrict__ Bh, const __nv_bfloat16* __restrict__ Bl,
             const float* __restrict__ bias, float* __restrict__ C,
             int N, int Ka)
{
    extern __shared__ char smem[];
    const uint32_t smb = smem_u32_(smem);
    const int tid = threadIdx.x;
    const int wid = tid >> 5, lane = tid & 31;
    const int wm = wid & 3, wn = wid >> 2;
    const int m0 = blockIdx.y * 128, n0 = blockIdx.x * 128;
    const int nchunk = Ka >> 5;

    const int lrow0 = tid >> 2,         lg0 = tid & 3;
    const int lrow1 = (tid + 256) >> 2, lg1 = (tid + 256) & 3;

    float acc[2][8][4];
#pragma unroll
    for (int mt = 0; mt < 2; mt++)
#pragma unroll
        for (int nt = 0; nt < 8; nt++)
#pragma unroll
            for (int q = 0; q < 4; q++) acc[mt][nt][q] = 0.0f;

    gts_pf_(smb, Ah, Al, Bh, Bl, m0, n0, 0, Ka, lrow0, lg0, lrow1, lg1);

    for (int c = 0; c < nchunk; ++c) {
        if (c + 1 < nchunk)
            gts_pf_(smb + (uint32_t)(((c + 1) & 1) * 40960),
                    Ah, Al, Bh, Bl, m0, n0, (c + 1) * 32, Ka, lrow0, lg0, lrow1, lg1);
        if (c + 1 < nchunk) cp_wait1_(); else cp_wait0_();
        __syncthreads();
        const uint32_t sb = smb + (uint32_t)((c & 1) * 40960);
#pragma unroll
        for (int ks = 0; ks < 2; ks++) {
            uint32_t aFh[2][4], aFl[2][4], bF[4][4];
#pragma unroll
            for (int mt = 0; mt < 2; mt++) {
                uint32_t ar = (uint32_t)((wm * 32 + mt * 16 + (lane & 15)) * 80
                                         + ((lane >> 4) * 16) + ks * 32);
                ldm4_(aFh[mt], sb + ar);
                ldm4_(aFl[mt], sb + 10240 + ar);
            }
            // load Bh frags
#pragma unroll
            for (int bt = 0; bt < 4; bt++) {
                uint32_t br = (uint32_t)((wn * 64 + bt * 16 + (lane & 7) + ((lane >> 4) << 3)) * 80
                                         + (((lane >> 3) & 1) * 16) + ks * 32);
                ldm4_(bF[bt], sb + 20480 + br);
            }
            // pass 1: Ah*Bh
#pragma unroll
            for (int mt = 0; mt < 2; mt++)
#pragma unroll
                for (int bt = 0; bt < 4; bt++) {
                    mma16816_(acc[mt][2 * bt],     aFh[mt], bF[bt][0], bF[bt][1]);
                    mma16816_(acc[mt][2 * bt + 1], aFh[mt], bF[bt][2], bF[bt][3]);
                }
            // pass 2: Al*Bh (bF still holds Bh)
#pragma unroll
            for (int mt = 0; mt < 2; mt++)
#pragma unroll
                for (int bt = 0; bt < 4; bt++) {
                    mma16816_(acc[mt][2 * bt],     aFl[mt], bF[bt][0], bF[bt][1]);
                    mma16816_(acc[mt][2 * bt + 1], aFl[mt], bF[bt][2], bF[bt][3]);
                }
            // reload bF with Bl
#pragma unroll
            for (int bt = 0; bt < 4; bt++) {
                uint32_t br = (uint32_t)((wn * 64 + bt * 16 + (lane & 7) + ((lane >> 4) << 3)) * 80
                                         + (((lane >> 3) & 1) * 16) + ks * 32);
                ldm4_(bF[bt], sb + 30720 + br);
            }
            // pass 3: Ah*Bl
#pragma unroll
            for (int mt = 0; mt < 2; mt++)
#pragma unroll
                for (int bt = 0; bt < 4; bt++) {
                    mma16816_(acc[mt][2 * bt],     aFh[mt], bF[bt][0], bF[bt][1]);
                    mma16816_(acc[mt][2 * bt + 1], aFh[mt], bF[bt][2], bF[bt][3]);
                }
        }
        __syncthreads();
    }

#pragma unroll
    for (int mt = 0; mt < 2; mt++) {
        int r0 = m0 + wm * 32 + mt * 16 + (lane >> 2);
        int r1 = r0 + 8;
#pragma unroll
        for (int nt = 0; nt < 8; nt++) {
            int n = n0 + wn * 64 + nt * 8 + 2 * (lane & 3);
            if (n < N) {
                float b0 = bias ? bias[n] : 0.0f;
                float b1 = bias ? bias[n + 1] : 0.0f;
                float2 v0 = make_float2(acc[mt][nt][0] + b0, acc[mt][nt][1] + b1);
                float2 v1 = make_float2(acc[mt][nt][2] + b0, acc[mt][nt][3] + b1);
                if (CMODE == 0) {
                    *(float2*)(C + (size_t)r0 * N + n) = v0;
                    *(float2*)(C + (size_t)r1 * N + n) = v1;
                } else {
                    *(float2*)(C + (size_t)((r0 & 127) * T_DEC + (r0 >> 7)) * D_W + n) = v0;
                    *(float2*)(C + (size_t)((r1 & 127) * T_DEC + (r1 >> 7)) * D_W + n) = v1;
                }
            }
        }
    }
}

// ============================ conversion kernels ============================
__device__ __forceinline__ void split_bf16_(float x, __nv_bfloat16* h, __nv_bfloat16* l) {
    __nv_bfloat16 hi = __float2bfloat16(x);
    *h = hi;
    *l = __float2bfloat16(x - __bfloat162float(hi));
}

__global__ void conv_frames(const float* __restrict__ frames,
                            __nv_bfloat16* __restrict__ Ah, __nv_bfloat16* __restrict__ Al)
{
    int m = blockIdx.x;
    int b = m & 127, t = m >> 7;
    const float* src = frames + (size_t)(b * T_ENC + t) * D_IN;
    size_t dst = (size_t)m * D_IN;
    for (int k = threadIdx.x; k < D_IN; k += blockDim.x)
        split_bf16_(src[k], &Ah[dst + k], &Al[dst + k]);
}

__global__ void conv_w_t(const float* __restrict__ W, int ldw, int Ksrc, int Kpad, int Nsrc,
                         __nv_bfloat16* __restrict__ Th, __nv_bfloat16* __restrict__ Tl)
{
    __shared__ float s[32][33];
    int k0 = blockIdx.x * 32, n0 = blockIdx.y * 32;
    int tx = threadIdx.x, ty = threadIdx.y;
#pragma unroll
    for (int j = 0; j < 4; j++) {
        int k = k0 + ty + j * 8, n = n0 + tx;
        s[ty + j * 8][tx] = (k < Ksrc && n < Nsrc) ? W[(size_t)k * ldw + n] : 0.0f;
    }
    __syncthreads();
#pragma unroll
    for (int j = 0; j < 4; j++) {
        int n = n0 + ty + j * 8, k = k0 + tx;
        split_bf16_(s[tx][ty + j * 8], &Th[(size_t)n * Kpad + k], &Tl[(size_t)n * Kpad + k]);
    }
}

// Wh [512 k][2048 cols (g*512+u)] -> WhT limbs [2048 rows (u*4+g)][512 k]
__global__ void conv_whT(const float* __restrict__ Wh,
                         __nv_bfloat16* __restrict__ Th, __nv_bfloat16* __restrict__ Tl)
{
    __shared__ float s[32][33];
    int k0 = blockIdx.x * 32, u0 = blockIdx.y * 32, g = blockIdx.z;
    int tx = threadIdx.x, ty = threadIdx.y;
#pragma unroll
    for (int j = 0; j < 4; j++) {
        int k = k0 + ty + j * 8;
        s[ty + j * 8][tx] = Wh[(size_t)k * G4 + g * H_SZ + u0 + tx];
    }
    __syncthreads();
#pragma unroll
    for (int j = 0; j < 4; j++) {
        int u = u0 + ty + j * 8;
        int r = u * 4 + g;
        split_bf16_(s[tx][ty + j * 8], &Th[(size_t)r * H_SZ + k0 + tx],
                                       &Tl[(size_t)r * H_SZ + k0 + tx]);
    }
}

__global__ void gather_conv(const int* __restrict__ ids, const float* __restrict__ emb,
                            __nv_bfloat16* __restrict__ Ah, __nv_bfloat16* __restrict__ Al)
{
    int m = blockIdx.x;
    int t = m >> 7, b = m & 127;
    int id = ids[b * T_DEC + t];
    const float* src = emb + (size_t)id * D_W;
    size_t dst = (size_t)m * D_WP;
    for (int k = threadIdx.x; k < D_WP; k += blockDim.x) {
        float x = (k < D_W) ? src[k] : 0.0f;
        split_bf16_(x, &Ah[dst + k], &Al[dst + k]);
    }
}

// ============================ persistent tensor-core recurrence ============================
// grid (32,1,4) = 128 co-resident CTAs. CTA (bx,ks): 128 rows x 64 WhT-rows [bx*64..),
// K chunk ks*128. B (WhT limbs) resident in smem. Per step: stage Ah/Al as separate
// cp.async groups (Al load overlapped with Ah MMA passes), write P, bar, distributed
// pointwise (CTA cid owns batch b=cid), bar, swap parity.
#define REC_SMEM (2 * 17408 + 2 * 34816)

__global__ __launch_bounds__(256, 1)
void lstm_rec(const __nv_bfloat16* __restrict__ WTh, const __nv_bfloat16* __restrict__ WTl,
              const float* __restrict__ Xg0, int nsteps, int do_first,
              const __nv_bfloat16* inh, const __nv_bfloat16* inl,
              __nv_bfloat16* outh, __nv_bfloat16* outl,
              __nv_bfloat16* dh, __nv_bfloat16* dl)
{
    extern __shared__ char dsm[];
    const uint32_t Bsb = smem_u32_(dsm);                 // 2 limbs x 64 rows x 272B
    const uint32_t Asb = Bsb + 2 * 17408;                // 2 limbs x 128 rows x 272B
    const int tid = threadIdx.x;
    const int w = tid >> 5, lane = tid & 31;
    const int bx = blockIdx.x;
    const int ks = blockIdx.z;
    const int k0 = ks * 128;
    const int cid = ks * 32 + bx;
    const int n0row = bx * 64;

    // preload B limbs once
    {
        int row = tid >> 2;
#pragma unroll
        for (int i = 0; i < 4; i++) {
            int j = (tid & 3) * 4 + i;
            cp16_(Bsb + row * 272 + j * 16,         WTh + (size_t)(n0row + row) * H_SZ + k0 + j * 8);
            cp16_(Bsb + 17408 + row * 272 + j * 16, WTl + (size_t)(n0row + row) * H_SZ + k0 + j * 8);
        }
        cp_commit_(); cp_wait0_();
    }
    __syncthreads();

    const __nv_bfloat16* hin_h = inh; const __nv_bfloat16* hin_l = inl;
    __nv_bfloat16* hout_h = outh;     __nv_bfloat16* hout_l = outl;

    int tstart = 0;
    if (do_first) {   // step 0: pointwise only (h=0, c=0)
        const float* Xgt = Xg0 + (size_t)cid * G4;
#pragma unroll
        for (int e = 0; e < 2; e++) {
            int u = tid + e * 256;
            float gi = Xgt[u], gj = Xgt[512 + u], go = Xgt[1536 + u];
            float cn = fsig_(gi) * ftanh_(gj);
            float hn = ftanh_(cn) * fsig_(go);
            int hidx = cid * H_SZ + u;
            g_c[hidx] = cn;
            split_bf16_(hn, &hout_h[hidx], &hout_l[hidx]);
        }
        grid_bar4_(ks);
        const __nv_bfloat16* th = hout_h; const __nv_bfloat16* tl = hout_l;
        hout_h = (__nv_bfloat16*)hin_h; hout_l = (__nv_bfloat16*)hin_l;
        hin_h = th; hin_l = tl;
        tstart = 1;
    }

    for (int t = tstart; t < nsteps; ++t) {
        // stage Ah then Al as separate commit groups
        {
            int row = tid >> 1;
#pragma unroll
            for (int i = 0; i < 8; i++) {
                int j = (tid & 1) * 8 + i;
                cp16_(Asb + row * 272 + j * 16, hin_h + (size_t)row * H_SZ + k0 + j * 8);
            }
            cp_commit_();
#pragma unroll
            for (int i = 0; i < 8; i++) {
                int j = (tid & 1) * 8 + i;
                cp16_(Asb + 34816 + row * 272 + j * 16, hin_l + (size_t)row * H_SZ + k0 + j * 8);
            }
            cp_commit_();
        }
        cp_wait1_();           // Ah ready; Al still in flight
        __syncthreads();

        float acc[8][4];
#pragma unroll
        for (int nt = 0; nt < 8; nt++)
#pragma unroll
            for (int q = 0; q < 4; q++) acc[nt][q] = 0.0f;

        // loop 1: Ah passes against Bh and Bl (Al load overlapped)
#pragma unroll
        for (int kk = 0; kk < 8; kk++) {
            uint32_t aFh[4], bFh[4][4], bFl[4][4];
            uint32_t ar = Asb + (uint32_t)((w * 16 + (lane & 15)) * 272 + kk * 32 + ((lane >> 4) << 4));
            ldm4_(aFh, ar);
#pragma unroll
            for (int bt = 0; bt < 4; bt++) {
                uint32_t br = Bsb + (uint32_t)((bt * 16 + (lane & 7) + ((lane >> 4) << 3)) * 272
                                               + (((lane >> 3) & 1) << 4) + kk * 32);
                ldm4_(bFh[bt], br);
                ldm4_(bFl[bt], br + 17408);
            }
#pragma unroll
            for (int bt = 0; bt < 4; bt++) {
                mma16816_(acc[2 * bt],     aFh, bFh[bt][0], bFh[bt][1]);
                mma16816_(acc[2 * bt + 1], aFh, bFh[bt][2], bFh[bt][3]);
            }
#pragma unroll
            for (int bt = 0; bt < 4; bt++) {
                mma16816_(acc[2 * bt],     aFh, bFl[bt][0], bFl[bt][1]);
                mma16816_(acc[2 * bt + 1], aFh, bFl[bt][2], bFl[bt][3]);
            }
        }
        cp_wait0_();           // Al ready
        __syncthreads();

        // loop 2: Al*Bh pass
#pragma unroll
        for (int kk = 0; kk < 8; kk++) {
            uint32_t aFl[4], bFh[4][4];
            uint32_t ar = Asb + 34816
                        + (uint32_t)((w * 16 + (lane & 15)) * 272 + kk * 32 + ((lane >> 4) << 4));
            ldm4_(aFl, ar);
#pragma unroll
            for (int bt = 0; bt < 4; bt++) {
                uint32_t br = Bsb + (uint32_t)((bt * 16 + (lane & 7) + ((lane >> 4) << 3)) * 272
                                               + (((lane >> 3) & 1) << 4) + kk * 32);
                ldm4_(bFh[bt], br);
            }
#pragma unroll
            for (int bt = 0; bt < 4; bt++) {
                mma16816_(acc[2 * bt],     aFl, bFh[bt][0], bFh[bt][1]);
                mma16816_(acc[2 * bt + 1], aFl, bFh[bt][2], bFh[bt][3]);
            }
        }
        __syncthreads();

        // write P partials (cols gate-interleaved: n_global = u*4+g)
        {
            int r0w = w * 16 + (lane >> 2);
            float* pp = g_P + (size_t)ks * (B_SZ * G4);
#pragma unroll
            for (int nt = 0; nt < 8; nt++) {
                int n = n0row + nt * 8 + (lane & 3) * 2;
                *(float2*)(pp + (size_t)r0w * G4 + n)       = make_float2(acc[nt][0], acc[nt][1]);
                *(float2*)(pp + (size_t)(r0w + 8) * G4 + n) = make_float2(acc[nt][2], acc[nt][3]);
            }
        }
        grid_bar4_(ks);

        // distributed pointwise: CTA cid owns batch b=cid
        {
            const float* Xgt = Xg0 + (size_t)t * (B_SZ * G4) + (size_t)cid * G4;
#pragma unroll
            for (int e = 0; e < 2; e++) {
                int u = tid + e * 256;
                float gi = Xgt[u], gj = Xgt[512 + u], gf = Xgt[1024 + u], go = Xgt[1536 + u];
                size_t pb = (size_t)cid * G4 + (size_t)u * 4;
#pragma unroll
                for (int s = 0; s < 4; s++) {
                    float4 q = __ldcg((const float4*)(g_P + (size_t)s * (B_SZ * G4) + pb));
                    gi += q.x; gj += q.y; gf += q.z; go += q.w;
                }
                int hidx = cid * H_SZ + u;
                float cn = g_c[hidx] * fsig_(gf + 1.0f) + fsig_(gi) * ftanh_(gj);
                float hn = ftanh_(cn) * fsig_(go);
                g_c[hidx] = cn;
                __nv_bfloat16 hh = __float2bfloat16(hn);
                __nv_bfloat16 hl = __float2bfloat16(hn - __bfloat162float(hh));
                hout_h[hidx] = hh;
                hout_l[hidx] = hl;
                if (dh) {
                    dh[(size_t)t * (B_SZ * H_SZ) + hidx] = hh;
                    dl[(size_t)t * (B_SZ * H_SZ) + hidx] = hl;
                }
            }
        }
        grid_bar4_(ks);
        {   // swap parity
            const __nv_bfloat16* th = hin_h; const __nv_bfloat16* tl = hin_l;
            hin_h = hout_h; hin_l = hout_l;
            hout_h = (__nv_bfloat16*)th; hout_l = (__nv_bfloat16*)tl;
        }
    }
}

// ============================ host launcher ============================
extern "C" void kernel_launch(void* const* d_in, const int* in_sizes, int n_in,
                              void* d_out, int out_size)
{
    (void)in_sizes; (void)n_in; (void)out_size;
    const float* frames = (const float*)d_in[0];
    const int*   ids    = (const int*)d_in[1];
    const float* emb    = (const float*)d_in[2];
    const float* W_enc  = (const float*)d_in[3];
    const float* b_enc  = (const float*)d_in[4];
    const float* W_dec  = (const float*)d_in[5];
    const float* b_dec  = (const float*)d_in[6];
    const float* W_out  = (const float*)d_in[7];
    const float* b_out  = (const float*)d_in[8];
    float* out = (float*)d_out;

    float *Xge, *Xgd;
    __nv_bfloat16 *Afh, *Afl, *Beh, *Bel, *Adh, *Adl, *Bdh, *Bdl, *Dhh, *Dhl, *Boh, *Bol;
    __nv_bfloat16 *WhT, *hl;
    cudaGetSymbolAddress((void**)&Xge, g_Xg_enc);
    cudaGetSymbolAddress((void**)&Xgd, g_Xg_dec);
    cudaGetSymbolAddress((void**)&WhT, g_WhT);
    cudaGetSymbolAddress((void**)&hl,  g_hl);
    cudaGetSymbolAddress((void**)&Afh, g_Afr_h);  cudaGetSymbolAddress((void**)&Afl, g_Afr_l);
    cudaGetSymbolAddress((void**)&Beh, g_Bte_h);  cudaGetSymbolAddress((void**)&Bel, g_Bte_l);
    cudaGetSymbolAddress((void**)&Adh, g_Ad_h);   cudaGetSymbolAddress((void**)&Adl, g_Ad_l);
    cudaGetSymbolAddress((void**)&Bdh, g_Btd_h);  cudaGetSymbolAddress((void**)&Bdl, g_Btd_l);
    cudaGetSymbolAddress((void**)&Dhh, g_Dh_h);   cudaGetSymbolAddress((void**)&Dhl, g_Dh_l);
    cudaGetSymbolAddress((void**)&Boh, g_Bto_h);  cudaGetSymbolAddress((void**)&Bol, g_Bto_l);

    const size_t WL = (size_t)G4 * H_SZ;
    __nv_bfloat16* WTeh = WhT;            __nv_bfloat16* WTel = WhT + WL;
    __nv_bfloat16* WTdh = WhT + 2 * WL;   __nv_bfloat16* WTdl = WhT + 3 * WL;
    const size_t HL = (size_t)B_SZ * H_SZ;
    __nv_bfloat16* h0h = hl;             __nv_bfloat16* h0l = hl + HL;
    __nv_bfloat16* h1h = hl + 2 * HL;    __nv_bfloat16* h1l = hl + 3 * HL;

    cudaFuncSetAttribute(gemm_ts<0>, cudaFuncAttributeMaxDynamicSharedMemorySize, GTS_SMEM);
    cudaFuncSetAttribute(gemm_ts<1>, cudaFuncAttributeMaxDynamicSharedMemorySize, GTS_SMEM);
    cudaFuncSetAttribute(lstm_rec,   cudaFuncAttributeMaxDynamicSharedMemorySize, REC_SMEM);

    // conversions
    conv_frames<<<M_ENC, 256>>>(frames, Afh, Afl);
    conv_w_t<<<dim3(D_IN / 32, G4 / 32), dim3(32, 8)>>>(W_enc, G4, D_IN, D_IN, G4, Beh, Bel);
    conv_w_t<<<dim3(D_WP / 32, G4 / 32), dim3(32, 8)>>>(W_dec, G4, D_W, D_WP, G4, Bdh, Bdl);
    conv_w_t<<<dim3(H_SZ / 32, 512 / 32), dim3(32, 8)>>>(W_out, D_W, H_SZ, H_SZ, D_W, Boh, Bol);
    conv_whT<<<dim3(16, 16, 4), dim3(32, 8)>>>(W_enc + (size_t)D_IN * G4, WTeh, WTel);
    conv_whT<<<dim3(16, 16, 4), dim3(32, 8)>>>(W_dec + (size_t)D_W * G4, WTdh, WTdl);
    gather_conv<<<M_DEC, 128>>>(ids, emb, Adh, Adl);

    // 1. Encoder input gates
    gemm_ts<0><<<dim3(G4 / 128, M_ENC / 128), 256, GTS_SMEM>>>(
        Afh, Afl, Beh, Bel, b_enc, Xge, G4, D_IN);

    // 2. Encoder recurrence (64 steps; step0 writes parity0 -> final h in parity1)
    lstm_rec<<<dim3(32, 1, 4), 256, REC_SMEM>>>(
        WTeh, WTel, Xge, T_ENC, 1, h1h, h1l, h0h, h0l, nullptr, nullptr);

    // 3. Decoder input gates
    gemm_ts<0><<<dim3(G4 / 128, M_DEC / 128), 256, GTS_SMEM>>>(
        Adh, Adl, Bdh, Bdl, b_dec, Xgd, G4, D_WP);

    // 4. Decoder recurrence (32 steps from encoder state in parity1), writes h limbs per t
    lstm_rec<<<dim3(32, 1, 4), 256, REC_SMEM>>>(
        WTdh, WTdl, Xgd, T_DEC, 0, h1h, h1l, h0h, h0l, Dhh, Dhl);

    // 5. Output projection, permuted store into [B, T_dec, D_w]
    gemm_ts<1><<<dim3(3, M_DEC / 128), 256, GTS_SMEM>>>(
        Dhh, Dhl, Boh, Bol, b_out, out, D_W, H_SZ);
}